// round 14
// baseline (speedup 1.0000x reference)
#include <cuda_runtime.h>
#include <cuda_bf16.h>
#include <math.h>
#include <cstdint>

#define SEQ    4096
#define HIDDEN 2048
#define NHEAD  16
#define NKVH   8
#define HDIM   128

// ===================== helpers ============================================
__device__ __forceinline__ uint32_t smem_to_u32(const void* p) {
    uint32_t a;
    asm("{ .reg .u64 t; cvta.to.shared.u64 t, %1; cvt.u32.u64 %0, t; }"
        : "=r"(a) : "l"(p));
    return a;
}
__device__ __forceinline__ void ldsm4(uint32_t* r, uint32_t addr) {
    asm volatile("ldmatrix.sync.aligned.m8n8.x4.shared.b16 {%0,%1,%2,%3}, [%4];"
        : "=r"(r[0]), "=r"(r[1]), "=r"(r[2]), "=r"(r[3]) : "r"(addr));
}
__device__ __forceinline__ void mma_bf16(float* c, const uint32_t* a,
                                         uint32_t b0, uint32_t b1) {
    asm volatile(
        "mma.sync.aligned.m16n8k16.row.col.f32.bf16.bf16.f32 "
        "{%0,%1,%2,%3}, {%4,%5,%6,%7}, {%8,%9}, {%0,%1,%2,%3};"
        : "+f"(c[0]), "+f"(c[1]), "+f"(c[2]), "+f"(c[3])
        : "r"(a[0]), "r"(a[1]), "r"(a[2]), "r"(a[3]), "r"(b0), "r"(b1));
}
__device__ __forceinline__ uint32_t pack_bf16(float x, float y) {
    __nv_bfloat162 t;
    t.x = __float2bfloat16(x); t.y = __float2bfloat16(y);
    return *(uint32_t*)&t;
}
__device__ __forceinline__ void cp16(uint32_t dst, const void* src) {
    asm volatile("cp.async.cg.shared.global [%0], [%1], 16;"
                 :: "r"(dst), "l"(src));
}
#define CP_COMMIT() asm volatile("cp.async.commit_group;" ::: "memory")
#define CP_WAIT1()  asm volatile("cp.async.wait_group 1;" ::: "memory")
#define CP_WAIT0()  asm volatile("cp.async.wait_group 0;" ::: "memory")

// ===================== scratch (static device globals) ====================
__device__ float g_q  [SEQ * NHEAD * HDIM];   // QKV split-K partial 0 / O partial 0
__device__ float g_q2 [SEQ * NHEAD * HDIM];   // QKV split-K partial 1 / O partial 1
__device__ float g_op2[SEQ * NHEAD * HDIM];   // O partial 2
__device__ float g_op3[SEQ * NHEAD * HDIM];   // O partial 3
__device__ float g_k  [SEQ * NKVH  * HDIM];
__device__ float g_k2 [SEQ * NKVH  * HDIM];
__device__ float g_v  [SEQ * NKVH  * HDIM];
__device__ float g_v2 [SEQ * NKVH  * HDIM];
__device__ float g_cos[SEQ * 64];
__device__ float g_sin[SEQ * 64];

__device__ __nv_bfloat16 g_hsh[SEQ * HIDDEN],          g_hsl[SEQ * HIDDEN];
__device__ __nv_bfloat16 g_wqh[NHEAD * HDIM * HIDDEN], g_wql[NHEAD * HDIM * HIDDEN];
__device__ __nv_bfloat16 g_wkh[NKVH * HDIM * HIDDEN],  g_wkl[NKVH * HDIM * HIDDEN];
__device__ __nv_bfloat16 g_wvh[NKVH * HDIM * HIDDEN],  g_wvl[NKVH * HDIM * HIDDEN];
__device__ __nv_bfloat16 g_woh[HIDDEN * NHEAD * HDIM], g_wol[HIDDEN * NHEAD * HDIM];
__device__ __nv_bfloat16 g_aoh[SEQ * NHEAD * HDIM],    g_aol[SEQ * NHEAD * HDIM];

__device__ __nv_bfloat16 g_qh2[SEQ * NHEAD * HDIM], g_ql2[SEQ * NHEAD * HDIM];
__device__ __nv_bfloat16 g_kh2[SEQ * NKVH * HDIM],  g_kl2[SEQ * NKVH * HDIM];
__device__ __nv_bfloat16 g_vth[NKVH * HDIM * SEQ],  g_vtl[NKVH * HDIM * SEQ];

// ===================== fp32 -> bf16 hi/lo splits ==========================
#define HS4 2097152
#define WQ4 1048576
#define WK4 524288
#define WV4 524288
#define WO4 1048576
#define TOTA4 (HS4 + WQ4 + WK4 + WV4)

__device__ __forceinline__ void split4(const float* __restrict__ x,
                                       __nv_bfloat16* __restrict__ h,
                                       __nv_bfloat16* __restrict__ l, int j)
{
    float4 v = ((const float4*)x)[j];
    __nv_bfloat16 h0 = __float2bfloat16(v.x);
    __nv_bfloat16 h1 = __float2bfloat16(v.y);
    __nv_bfloat16 h2 = __float2bfloat16(v.z);
    __nv_bfloat16 h3 = __float2bfloat16(v.w);
    __nv_bfloat16 l0 = __float2bfloat16(v.x - __bfloat162float(h0));
    __nv_bfloat16 l1 = __float2bfloat16(v.y - __bfloat162float(h1));
    __nv_bfloat16 l2 = __float2bfloat16(v.z - __bfloat162float(h2));
    __nv_bfloat16 l3 = __float2bfloat16(v.w - __bfloat162float(h3));
    ushort4 hv = make_ushort4(__bfloat16_as_ushort(h0), __bfloat16_as_ushort(h1),
                              __bfloat16_as_ushort(h2), __bfloat16_as_ushort(h3));
    ushort4 lv = make_ushort4(__bfloat16_as_ushort(l0), __bfloat16_as_ushort(l1),
                              __bfloat16_as_ushort(l2), __bfloat16_as_ushort(l3));
    *(ushort4*)(h + 4 * (size_t)j) = hv;
    *(ushort4*)(l + 4 * (size_t)j) = lv;
}

__global__ __launch_bounds__(256)
void split_a(const float* __restrict__ hs, const float* __restrict__ wq,
             const float* __restrict__ wk, const float* __restrict__ wv)
{
    int i = blockIdx.x * 256 + threadIdx.x;
    if (i >= TOTA4) return;
    if (i < HS4)                        split4(hs, g_hsh, g_hsl, i);
    else if (i < HS4 + WQ4)             split4(wq, g_wqh, g_wql, i - HS4);
    else if (i < HS4 + WQ4 + WK4)       split4(wk, g_wkh, g_wkl, i - HS4 - WQ4);
    else                                split4(wv, g_wvh, g_wvl, i - HS4 - WQ4 - WK4);
}

__global__ __launch_bounds__(256)
void split_wo(const float* __restrict__ wo)
{
    int i = blockIdx.x * 256 + threadIdx.x;
    if (i >= WO4) return;
    split4(wo, g_woh, g_wol, i);
}

// == bf16x3 GEMM, 128x128 CTA, 4 warps (64x64 each), K-chunk 32, 2 CTA/SM ==
#define LDG2    80                          // bytes per 32-elem bf16 row (+16 pad)
#define T128    (128 * LDG2)                // 10240 B
#define OFF_AH  0
#define OFF_AL  T128
#define OFF_BH  (2 * T128)
#define OFF_BL  (3 * T128)
#define STG_B   (4 * T128)                  // 40960 B
#define GEMM_SMEM (2 * STG_B)               // 81920 B -> 2 CTA/SM

__device__ __forceinline__ void gemm_core(
    const __nv_bfloat16* __restrict__ Ah, const __nv_bfloat16* __restrict__ Al,
    const __nv_bfloat16* __restrict__ Bh, const __nv_bfloat16* __restrict__ Bl,
    float* __restrict__ C, int N, int K, int bm, int bn,
    int kbase, int nch, char* smem)
{
    const uint32_t sb = smem_to_u32(smem);
    const int tid  = threadIdx.x;
    const int lane = tid & 31, wid = tid >> 5;
    const int wm = wid & 1, wn2 = wid >> 1;     // 2x2 warp grid, 64x64 each

    float acc[4][8][4];
#pragma unroll
    for (int mi = 0; mi < 4; mi++)
#pragma unroll
        for (int ni = 0; ni < 8; ni++)
#pragma unroll
            for (int q = 0; q < 4; q++) acc[mi][ni][q] = 0.f;

    const int ldr = tid >> 2, seg = tid & 3;    // ldr: 0..31, seg: 0..3

    auto cp_stage = [&](int c, int stg) {
        const int k0 = kbase + c * 32;
        const uint32_t dbase = sb + stg * STG_B;
#pragma unroll
        for (int p = 0; p < 4; p++) {
            int r = ldr + p * 32;
            uint32_t doff = r * LDG2 + seg * 16;
            size_t ga = (size_t)(bm + r) * K + k0 + seg * 8;
            size_t gb = (size_t)(bn + r) * K + k0 + seg * 8;
            cp16(dbase + OFF_AH + doff, Ah + ga);
            cp16(dbase + OFF_AL + doff, Al + ga);
            cp16(dbase + OFF_BH + doff, Bh + gb);
            cp16(dbase + OFF_BL + doff, Bl + gb);
        }
        CP_COMMIT();
    };

    auto compute = [&](int stg) {
        const uint32_t base = sb + stg * STG_B;
        const int ksb = wid & 1;                // warp phase skew (2 phases)
#pragma unroll
        for (int ks2 = 0; ks2 < 2; ks2++) {
            const int ks = ks2 ^ ksb;
            uint32_t aH[4][4], aL[4][4];
            const uint32_t acol = (uint32_t)ks * 32 + (lane >> 4) * 16;
#pragma unroll
            for (int mi = 0; mi < 4; mi++) {
                uint32_t off = (uint32_t)(wm * 64 + mi * 16 + (lane & 15)) *
                               LDG2 + acol;
                ldsm4(aH[mi], base + OFF_AH + off);
                ldsm4(aL[mi], base + OFF_AL + off);
            }
            const uint32_t bcol = (uint32_t)ks * 32 + ((lane >> 3) & 1) * 16;
#pragma unroll
            for (int nt = 0; nt < 4; nt++) {
                int brow = wn2 * 64 + nt * 16 + (lane & 7) + ((lane >> 4) << 3);
                uint32_t off = (uint32_t)brow * LDG2 + bcol;
                uint32_t bh[4], bl[4];
                ldsm4(bh, base + OFF_BH + off);
                ldsm4(bl, base + OFF_BL + off);
#pragma unroll
                for (int mi = 0; mi < 4; mi++) {
                    mma_bf16(acc[mi][2 * nt],     aH[mi], bh[0], bh[1]);
                    mma_bf16(acc[mi][2 * nt],     aH[mi], bl[0], bl[1]);
                    mma_bf16(acc[mi][2 * nt],     aL[mi], bh[0], bh[1]);
                    mma_bf16(acc[mi][2 * nt + 1], aH[mi], bh[2], bh[3]);
                    mma_bf16(acc[mi][2 * nt + 1], aH[mi], bl[2], bl[3]);
                    mma_bf16(acc[mi][2 * nt + 1], aL[mi], bh[2], bh[3]);
                }
            }
        }
    };

    cp_stage(0, 0);
    cp_stage(1, 1);
    CP_WAIT1();
    __syncthreads();

    for (int c = 0; c < nch; c++) {
        compute(c & 1);
        if (c + 1 < nch) {
            __syncthreads();
            if (c + 2 < nch) { cp_stage(c + 2, c & 1); CP_WAIT1(); }
            else             { CP_WAIT0(); }
            __syncthreads();
        }
    }

    const int rbase = bm + wm * 64 + (lane >> 2);
    const int cbase = bn + wn2 * 64 + 2 * (lane & 3);
#pragma unroll
    for (int mi = 0; mi < 4; mi++)
#pragma unroll
        for (int ni = 0; ni < 8; ni++) {
            int r0 = rbase + mi * 16, cc = cbase + ni * 8;
            *(float2*)(C + (size_t)r0 * N + cc) =
                make_float2(acc[mi][ni][0], acc[mi][ni][1]);
            *(float2*)(C + (size_t)(r0 + 8) * N + cc) =
                make_float2(acc[mi][ni][2], acc[mi][ni][3]);
        }
}

// fused QKV, split-K=2: grid (32, 64); y -> (kh, mtile)
__global__ __launch_bounds__(128, 2)
void qkv_gemm()
{
    extern __shared__ __align__(128) char smem[];
    const int bx = blockIdx.x;
    const int kh = blockIdx.y & 1;
    const int my = blockIdx.y >> 1;
    const __nv_bfloat16 *Bh, *Bl;
    float* C;
    int Nout, bn;
    if (bx < 16)      { Bh = g_wqh; Bl = g_wql; C = kh ? g_q2 : g_q; Nout = 2048; bn = bx * 128; }
    else if (bx < 24) { Bh = g_wkh; Bl = g_wkl; C = kh ? g_k2 : g_k; Nout = 1024; bn = (bx - 16) * 128; }
    else              { Bh = g_wvh; Bl = g_wvl; C = kh ? g_v2 : g_v; Nout = 1024; bn = (bx - 24) * 128; }
    gemm_core(g_hsh, g_hsl, Bh, Bl, C, Nout, HIDDEN, my * 128, bn,
              kh * 1024, 32, smem);
}

// O projection, split-K=4: grid (16, 128); y -> (kq, mtile)
__global__ __launch_bounds__(128, 2)
void o_gemm()
{
    extern __shared__ __align__(128) char smem[];
    const int kq = blockIdx.y & 3;
    const int my = blockIdx.y >> 2;
    float* part[4];
    part[0] = g_q; part[1] = g_q2; part[2] = g_op2; part[3] = g_op3;
    gemm_core(g_aoh, g_aol, g_woh, g_wol, part[kq], HIDDEN, NHEAD * HDIM,
              my * 128, blockIdx.x * 128, kq * 512, 16, smem);
}

// sum 4 O partials -> out
__global__ __launch_bounds__(256)
void add4(float* __restrict__ out)
{
    int i = blockIdx.x * 256 + threadIdx.x;   // float4 index, n = 2097152
    float4 a = ((const float4*)g_q)[i];
    float4 b = ((const float4*)g_q2)[i];
    float4 c = ((const float4*)g_op2)[i];
    float4 d = ((const float4*)g_op3)[i];
    ((float4*)out)[i] = make_float4(a.x + b.x + c.x + d.x,
                                    a.y + b.y + c.y + d.y,
                                    a.z + b.z + c.z + d.z,
                                    a.w + b.w + c.w + d.w);
}

// ===================== RoPE table =========================================
__global__ void rope_table_kernel()
{
    int idx = blockIdx.x * 256 + threadIdx.x;
    if (idx >= SEQ * 64) return;
    int s = idx >> 6, f = idx & 63;
    double invf = pow(1.0e6, -(double)f / 64.0);
    float ang = (float)s * (float)invf;
    g_cos[idx] = (float)cos((double)ang);
    g_sin[idx] = (float)sin((double)ang);
}

// ======= per-(s,head) RMSNorm + RoPE on (X0+X1) -> bf16 hi/lo =============
__global__ __launch_bounds__(128)
void qk_norm_rope_split(const float* __restrict__ X0, const float* __restrict__ X1,
                        const float* __restrict__ W,
                        __nv_bfloat16* __restrict__ Xh, __nv_bfloat16* __restrict__ Xl,
                        int nh, float scale)
{
    const int s = blockIdx.x, hh = blockIdx.y, d = threadIdx.x;
    const size_t off = ((size_t)s * nh + hh) * HDIM + d;
    float v = X0[off] + X1[off];

    float ss = v * v;
#pragma unroll
    for (int o = 16; o > 0; o >>= 1) ss += __shfl_xor_sync(0xffffffffu, ss, o);
    __shared__ float wsum[4];
    __shared__ float sh[128];
    if ((d & 31) == 0) wsum[d >> 5] = ss;
    __syncthreads();
    float tot = wsum[0] + wsum[1] + wsum[2] + wsum[3];
    float r = rsqrtf(tot * (1.0f / 128.0f) + 1e-6f);
    v = v * r * W[d];

    sh[d] = v;
    __syncthreads();
    int f = d & 63;
    float c  = g_cos[s * 64 + f];
    float sn = g_sin[s * 64 + f];
    float o2 = sh[d ^ 64];
    float out = ((d < 64) ? (v * c - o2 * sn) : (v * c + o2 * sn)) * scale;

    __nv_bfloat16 hi = __float2bfloat16(out);
    Xh[off] = hi;
    Xl[off] = __float2bfloat16(out - __bfloat162float(hi));
}

// ==== V: (V0+V1) fp32 [s][kvh][d] -> bf16 hi/lo transposed [kvh][d][s] ====
__global__ __launch_bounds__(256)
void v_split_t(const float* __restrict__ V0, const float* __restrict__ V1,
               __nv_bfloat16* __restrict__ Vth, __nv_bfloat16* __restrict__ Vtl)
{
    __shared__ float t[32][33];
    const int s0 = blockIdx.x * 32, d0 = blockIdx.y * 32, kvh = blockIdx.z;
    const int x = threadIdx.x, y = threadIdx.y;
#pragma unroll
    for (int yy = y; yy < 32; yy += 8) {
        size_t g = (size_t)(s0 + yy) * (NKVH * HDIM) + kvh * HDIM + d0 + x;
        t[x][yy] = V0[g] + V1[g];
    }
    __syncthreads();
#pragma unroll
    for (int yy = y; yy < 32; yy += 8) {
        float v = t[yy][x];
        __nv_bfloat16 hi = __float2bfloat16(v);
        size_t o = (size_t)kvh * HDIM * SEQ + (size_t)(d0 + yy) * SEQ + s0 + x;
        Vth[o] = hi;
        Vtl[o] = __float2bfloat16(v - __bfloat162float(hi));
    }
}

// ===================== flash attention on mma.sync (validated) ============
#define SKQ 136
#define SKV 72
#define FLASH_SMEM ((4 * 64 * SKQ + 2 * 128 * SKV) * 2)

__global__ __launch_bounds__(128)
void flash_mma(const __nv_bfloat16* __restrict__ Qh, const __nv_bfloat16* __restrict__ Ql,
               const __nv_bfloat16* __restrict__ Kh, const __nv_bfloat16* __restrict__ Kl,
               const __nv_bfloat16* __restrict__ Vth, const __nv_bfloat16* __restrict__ Vtl,
               __nv_bfloat16* __restrict__ Oh, __nv_bfloat16* __restrict__ Ol)
{
    extern __shared__ __align__(128) __nv_bfloat16 fsm[];
    __nv_bfloat16* sQh = fsm;
    __nv_bfloat16* sQl = sQh + 64 * SKQ;
    __nv_bfloat16* sKh = sQl + 64 * SKQ;
    __nv_bfloat16* sKl = sKh + 64 * SKQ;
    __nv_bfloat16* sVh = sKl + 64 * SKQ;
    __nv_bfloat16* sVl = sVh + 128 * SKV;

    const uint32_t bQh = smem_to_u32(sQh), bQl = smem_to_u32(sQl);
    const uint32_t bKh = smem_to_u32(sKh), bKl = smem_to_u32(sKl);
    const uint32_t bVh = smem_to_u32(sVh), bVl = smem_to_u32(sVl);

    const int h = blockIdx.y, kvh = h >> 1;
    const int qi = (int)gridDim.x - 1 - (int)blockIdx.x;
    const int tid = threadIdx.x, lane = tid & 31, warp = tid >> 5;

#pragma unroll
    for (int i = tid; i < 1024; i += 128) {
        int r = i >> 4, c = i & 15;
        size_t g = (size_t)(qi * 64 + r) * (NHEAD * HDIM) + h * HDIM + c * 8;
        *(uint4*)(sQh + r * SKQ + c * 8) = *(const uint4*)(Qh + g);
        *(uint4*)(sQl + r * SKQ + c * 8) = *(const uint4*)(Ql + g);
    }

    float o[16][4];
#pragma unroll
    for (int t = 0; t < 16; t++)
#pragma unroll
        for (int q = 0; q < 4; q++) o[t][q] = 0.f;
    float m0 = -1e30f, m1 = -1e30f, l0 = 0.f, l1 = 0.f;

    for (int j = 0; j <= qi; j++) {
        __syncthreads();
#pragma unroll
        for (int i = tid; i < 1024; i += 128) {
            int r = i >> 4, c = i & 15;
            size_t g = (size_t)(j * 64 + r) * (NKVH * HDIM) + kvh * HDIM + c * 8;
            *(uint4*)(sKh + r * SKQ + c * 8) = *(const uint4*)(Kh + g);
            *(uint4*)(sKl + r * SKQ + c * 8) = *(const uint4*)(Kl + g);
        }
#pragma unroll
        for (int i = tid; i < 1024; i += 128) {
            int r = i >> 3, c = i & 7;
            size_t g = (size_t)kvh * HDIM * SEQ + (size_t)r * SEQ + j * 64 + c * 8;
            *(uint4*)(sVh + r * SKV + c * 8) = *(const uint4*)(Vth + g);
            *(uint4*)(sVl + r * SKV + c * 8) = *(const uint4*)(Vtl + g);
        }
        __syncthreads();

        float s[8][4];
#pragma unroll
        for (int t = 0; t < 8; t++)
#pragma unroll
            for (int q = 0; q < 4; q++) s[t][q] = 0.f;

#pragma unroll
        for (int u = 0; u < 8; u++) {
            uint32_t aH[4], aL[4];
            uint32_t qoff = (uint32_t)(warp * 16 + (lane & 15)) * (SKQ * 2) +
                            u * 32 + (lane >> 4) * 16;
            ldsm4(aH, bQh + qoff);
            ldsm4(aL, bQl + qoff);
#pragma unroll
            for (int g = 0; g < 4; g++) {
                uint32_t koff = (uint32_t)(g * 16 + (lane & 7) + ((lane >> 4) << 3)) *
                                (SKQ * 2) + u * 32 + ((lane >> 3) & 1) * 16;
                uint32_t bh[4], bl[4];
                ldsm4(bh, bKh + koff);
                ldsm4(bl, bKl + koff);
                mma_bf16(s[2 * g],     aH, bh[0], bh[1]);
                mma_bf16(s[2 * g],     aH, bl[0], bl[1]);
                mma_bf16(s[2 * g],     aL, bh[0], bh[1]);
                mma_bf16(s[2 * g + 1], aH, bh[2], bh[3]);
                mma_bf16(s[2 * g + 1], aH, bl[2], bl[3]);
                mma_bf16(s[2 * g + 1], aL, bh[2], bh[3]);
            }
        }

        if (j == qi) {
            int lr = warp * 16 + (lane >> 2);
#pragma unroll
            for (int t = 0; t < 8; t++) {
                int c0 = 8 * t + 2 * (lane & 3);
                if (c0 > lr)          s[t][0] = -1e30f;
                if (c0 + 1 > lr)      s[t][1] = -1e30f;
                if (c0 > lr + 8)      s[t][2] = -1e30f;
                if (c0 + 1 > lr + 8)  s[t][3] = -1e30f;
            }
        }
        float mx0 = m0, mx1 = m1;
#pragma unroll
        for (int t = 0; t < 8; t++) {
            mx0 = fmaxf(mx0, fmaxf(s[t][0], s[t][1]));
            mx1 = fmaxf(mx1, fmaxf(s[t][2], s[t][3]));
        }
        mx0 = fmaxf(mx0, __shfl_xor_sync(0xffffffffu, mx0, 1));
        mx0 = fmaxf(mx0, __shfl_xor_sync(0xffffffffu, mx0, 2));
        mx1 = fmaxf(mx1, __shfl_xor_sync(0xffffffffu, mx1, 1));
        mx1 = fmaxf(mx1, __shfl_xor_sync(0xffffffffu, mx1, 2));

        float a0 = __expf(m0 - mx0), a1 = __expf(m1 - mx1);
        m0 = mx0; m1 = mx1;

        float rs0 = 0.f, rs1 = 0.f;
        uint32_t pH[4][4], pL[4][4];
#pragma unroll
        for (int t = 0; t < 8; t++) {
            float p0 = __expf(s[t][0] - mx0), p1 = __expf(s[t][1] - mx0);
            float p2 = __expf(s[t][2] - mx1), p3 = __expf(s[t][3] - mx1);
            rs0 += p0 + p1; rs1 += p2 + p3;
            float h0 = __bfloat162float(__float2bfloat16(p0));
            float h1 = __bfloat162float(__float2bfloat16(p1));
            float h2 = __bfloat162float(__float2bfloat16(p2));
            float h3 = __bfloat162float(__float2bfloat16(p3));
            int u = t >> 1, e = (t & 1) * 2;
            pH[u][e]     = pack_bf16(h0, h1);
            pH[u][e + 1] = pack_bf16(h2, h3);
            pL[u][e]     = pack_bf16(p0 - h0, p1 - h1);
            pL[u][e + 1] = pack_bf16(p2 - h2, p3 - h3);
        }
        rs0 += __shfl_xor_sync(0xffffffffu, rs0, 1);
        rs0 += __shfl_xor_sync(0xffffffffu, rs0, 2);
        rs1 += __shfl_xor_sync(0xffffffffu, rs1, 1);
        rs1 += __shfl_xor_sync(0xffffffffu, rs1, 2);
        l0 = l0 * a0 + rs0;
        l1 = l1 * a1 + rs1;
#pragma unroll
        for (int t = 0; t < 16; t++) {
            o[t][0] *= a0; o[t][1] *= a0; o[t][2] *= a1; o[t][3] *= a1;
        }

#pragma unroll
        for (int u = 0; u < 4; u++) {
#pragma unroll
            for (int g = 0; g < 8; g++) {
                uint32_t voff = (uint32_t)(g * 16 + (lane & 7) + ((lane >> 4) << 3)) *
                                (SKV * 2) + u * 32 + ((lane >> 3) & 1) * 16;
                uint32_t bh[4], bl[4];
                ldsm4(bh, bVh + voff);
                ldsm4(bl, bVl + voff);
                mma_bf16(o[2 * g],     pH[u], bh[0], bh[1]);
                mma_bf16(o[2 * g],     pH[u], bl[0], bl[1]);
                mma_bf16(o[2 * g],     pL[u], bh[0], bh[1]);
                mma_bf16(o[2 * g + 1], pH[u], bh[2], bh[3]);
                mma_bf16(o[2 * g + 1], pH[u], bl[2], bl[3]);
                mma_bf16(o[2 * g + 1], pL[u], bh[2], bh[3]);
            }
        }
    }

    float inv0 = 1.f / l0, inv1 = 1.f / l1;
    int r = qi * 64 + warp * 16 + (lane >> 2);
#pragma unroll
    for (int t = 0; t < 16; t++) {
        int d = 8 * t + 2 * (lane & 3);
        size_t o0 = (size_t)r * (NHEAD * HDIM) + h * HDIM + d;
        size_t o1 = (size_t)(r + 8) * (NHEAD * HDIM) + h * HDIM + d;
        float v0 = o[t][0] * inv0, v1 = o[t][1] * inv0;
        float v2 = o[t][2] * inv1, v3 = o[t][3] * inv1;
        float h0 = __bfloat162float(__float2bfloat16(v0));
        float h1 = __bfloat162float(__float2bfloat16(v1));
        float h2 = __bfloat162float(__float2bfloat16(v2));
        float h3 = __bfloat162float(__float2bfloat16(v3));
        *(uint32_t*)(Oh + o0) = pack_bf16(h0, h1);
        *(uint32_t*)(Ol + o0) = pack_bf16(v0 - h0, v1 - h1);
        *(uint32_t*)(Oh + o1) = pack_bf16(h2, h3);
        *(uint32_t*)(Ol + o1) = pack_bf16(v2 - h2, v3 - h3);
    }
}

// ===========================================================================
extern "C" void kernel_launch(void* const* d_in, const int* in_sizes, int n_in,
                              void* d_out, int out_size)
{
    const float* hs  = (const float*)d_in[0];
    const float* wq  = (const float*)d_in[2];
    const float* wk  = (const float*)d_in[3];
    const float* wv  = (const float*)d_in[4];
    const float* wo  = (const float*)d_in[5];
    const float* qnw = (const float*)d_in[6];
    const float* knw = (const float*)d_in[7];
    float* out = (float*)d_out;

    float *gq, *gq2, *gk, *gk2, *gv, *gv2;
    cudaGetSymbolAddress((void**)&gq,  g_q);  cudaGetSymbolAddress((void**)&gq2, g_q2);
    cudaGetSymbolAddress((void**)&gk,  g_k);  cudaGetSymbolAddress((void**)&gk2, g_k2);
    cudaGetSymbolAddress((void**)&gv,  g_v);  cudaGetSymbolAddress((void**)&gv2, g_v2);

    __nv_bfloat16 *aoh, *aol, *qh2, *ql2, *kh2, *kl2, *vth, *vtl;
    cudaGetSymbolAddress((void**)&aoh, g_aoh); cudaGetSymbolAddress((void**)&aol, g_aol);
    cudaGetSymbolAddress((void**)&qh2, g_qh2); cudaGetSymbolAddress((void**)&ql2, g_ql2);
    cudaGetSymbolAddress((void**)&kh2, g_kh2); cudaGetSymbolAddress((void**)&kl2, g_kl2);
    cudaGetSymbolAddress((void**)&vth, g_vth); cudaGetSymbolAddress((void**)&vtl, g_vtl);

    cudaFuncSetAttribute(qkv_gemm,
                         cudaFuncAttributeMaxDynamicSharedMemorySize, GEMM_SMEM);
    cudaFuncSetAttribute(o_gemm,
                         cudaFuncAttributeMaxDynamicSharedMemorySize, GEMM_SMEM);
    cudaFuncSetAttribute(flash_mma,
                         cudaFuncAttributeMaxDynamicSharedMemorySize, FLASH_SMEM);

    // 1. RoPE table
    rope_table_kernel<<<SEQ * 64 / 256, 256>>>();
    // 2. split hs + wq + wk + wv
    split_a<<<TOTA4 / 256, 256>>>(hs, wq, wk, wv);
    // 3. split wo
    split_wo<<<WO4 / 256, 256>>>(wo);
    // 4. fused QKV projection, split-K=2, 2 CTA/SM  <- ncu capture slot
    qkv_gemm<<<dim3(32, 64), 128, GEMM_SMEM>>>();
    // 5-7. RMSNorm+RoPE on summed partials -> bf16 operands; V transpose+split
    qk_norm_rope_split<<<dim3(SEQ, NHEAD), 128>>>(gq, gq2, qnw, qh2, ql2, NHEAD,
                                                  0.08838834764831845f);
    qk_norm_rope_split<<<dim3(SEQ, NKVH), 128>>>(gk, gk2, knw, kh2, kl2, NKVH, 1.0f);
    v_split_t<<<dim3(SEQ / 32, HDIM / 32, NKVH), dim3(32, 8)>>>(gv, gv2, vth, vtl);
    // 8. flash attention -> bf16 hi/lo AO
    flash_mma<<<dim3(SEQ / 64, NHEAD), 128, FLASH_SMEM>>>(qh2, ql2, kh2, kl2,
                                                          vth, vtl, aoh, aol);
    // 9. O projection, split-K=4 into partials (reuses g_q/g_q2 + g_op2/g_op3)
    o_gemm<<<dim3(16, 128), 128, GEMM_SMEM>>>();
    // 10. sum partials -> out
    add4<<<SEQ * HIDDEN / 1024, 256>>>(out);
}

// round 15
// speedup vs baseline: 1.0124x; 1.0124x over previous
#include <cuda_runtime.h>
#include <cuda_bf16.h>
#include <math.h>
#include <cstdint>

#define SEQ    4096
#define HIDDEN 2048
#define NHEAD  16
#define NKVH   8
#define HDIM   128

// ===================== helpers ============================================
__device__ __forceinline__ uint32_t smem_to_u32(const void* p) {
    uint32_t a;
    asm("{ .reg .u64 t; cvta.to.shared.u64 t, %1; cvt.u32.u64 %0, t; }"
        : "=r"(a) : "l"(p));
    return a;
}
__device__ __forceinline__ void ldsm4(uint32_t* r, uint32_t addr) {
    asm volatile("ldmatrix.sync.aligned.m8n8.x4.shared.b16 {%0,%1,%2,%3}, [%4];"
        : "=r"(r[0]), "=r"(r[1]), "=r"(r[2]), "=r"(r[3]) : "r"(addr));
}
__device__ __forceinline__ void mma_bf16(float* c, const uint32_t* a,
                                         uint32_t b0, uint32_t b1) {
    asm volatile(
        "mma.sync.aligned.m16n8k16.row.col.f32.bf16.bf16.f32 "
        "{%0,%1,%2,%3}, {%4,%5,%6,%7}, {%8,%9}, {%0,%1,%2,%3};"
        : "+f"(c[0]), "+f"(c[1]), "+f"(c[2]), "+f"(c[3])
        : "r"(a[0]), "r"(a[1]), "r"(a[2]), "r"(a[3]), "r"(b0), "r"(b1));
}
__device__ __forceinline__ uint32_t pack_bf16(float x, float y) {
    __nv_bfloat162 t;
    t.x = __float2bfloat16(x); t.y = __float2bfloat16(y);
    return *(uint32_t*)&t;
}
__device__ __forceinline__ void cp16(uint32_t dst, const void* src) {
    asm volatile("cp.async.cg.shared.global [%0], [%1], 16;"
                 :: "r"(dst), "l"(src));
}
#define CP_COMMIT() asm volatile("cp.async.commit_group;" ::: "memory")
#define CP_WAIT1()  asm volatile("cp.async.wait_group 1;" ::: "memory")
#define CP_WAIT0()  asm volatile("cp.async.wait_group 0;" ::: "memory")

// ===================== scratch (static device globals) ====================
__device__ float g_q  [SEQ * NHEAD * HDIM];   // QKV partial 0 / O partial 0
__device__ float g_q2 [SEQ * NHEAD * HDIM];   // QKV partial 1 / O partial 1
__device__ float g_op2[SEQ * NHEAD * HDIM];   // O partial 2
__device__ float g_op3[SEQ * NHEAD * HDIM];   // O partial 3
__device__ float g_k  [SEQ * NKVH  * HDIM];
__device__ float g_k2 [SEQ * NKVH  * HDIM];
__device__ float g_v  [SEQ * NKVH  * HDIM];
__device__ float g_v2 [SEQ * NKVH  * HDIM];
__device__ float g_cos[SEQ * 64];
__device__ float g_sin[SEQ * 64];

__device__ __nv_bfloat16 g_hsh[SEQ * HIDDEN],          g_hsl[SEQ * HIDDEN];
__device__ __nv_bfloat16 g_wqh[NHEAD * HDIM * HIDDEN], g_wql[NHEAD * HDIM * HIDDEN];
__device__ __nv_bfloat16 g_wkh[NKVH * HDIM * HIDDEN],  g_wkl[NKVH * HDIM * HIDDEN];
__device__ __nv_bfloat16 g_wvh[NKVH * HDIM * HIDDEN],  g_wvl[NKVH * HDIM * HIDDEN];
__device__ __nv_bfloat16 g_woh[HIDDEN * NHEAD * HDIM], g_wol[HIDDEN * NHEAD * HDIM];
__device__ __nv_bfloat16 g_aoh[SEQ * NHEAD * HDIM],    g_aol[SEQ * NHEAD * HDIM];

__device__ __nv_bfloat16 g_qh2[SEQ * NHEAD * HDIM], g_ql2[SEQ * NHEAD * HDIM];
__device__ __nv_bfloat16 g_kh2[SEQ * NKVH * HDIM],  g_kl2[SEQ * NKVH * HDIM];
__device__ __nv_bfloat16 g_vth[NKVH * HDIM * SEQ],  g_vtl[NKVH * HDIM * SEQ];

// ===================== fp32 -> bf16 hi/lo splits ==========================
#define HS4 2097152
#define WQ4 1048576
#define WK4 524288
#define WV4 524288
#define WO4 1048576
#define TOTA4 (HS4 + WQ4 + WK4 + WV4)

__device__ __forceinline__ void split4(const float* __restrict__ x,
                                       __nv_bfloat16* __restrict__ h,
                                       __nv_bfloat16* __restrict__ l, int j)
{
    float4 v = ((const float4*)x)[j];
    __nv_bfloat16 h0 = __float2bfloat16(v.x);
    __nv_bfloat16 h1 = __float2bfloat16(v.y);
    __nv_bfloat16 h2 = __float2bfloat16(v.z);
    __nv_bfloat16 h3 = __float2bfloat16(v.w);
    __nv_bfloat16 l0 = __float2bfloat16(v.x - __bfloat162float(h0));
    __nv_bfloat16 l1 = __float2bfloat16(v.y - __bfloat162float(h1));
    __nv_bfloat16 l2 = __float2bfloat16(v.z - __bfloat162float(h2));
    __nv_bfloat16 l3 = __float2bfloat16(v.w - __bfloat162float(h3));
    ushort4 hv = make_ushort4(__bfloat16_as_ushort(h0), __bfloat16_as_ushort(h1),
                              __bfloat16_as_ushort(h2), __bfloat16_as_ushort(h3));
    ushort4 lv = make_ushort4(__bfloat16_as_ushort(l0), __bfloat16_as_ushort(l1),
                              __bfloat16_as_ushort(l2), __bfloat16_as_ushort(l3));
    *(ushort4*)(h + 4 * (size_t)j) = hv;
    *(ushort4*)(l + 4 * (size_t)j) = lv;
}

__global__ __launch_bounds__(256)
void split_a(const float* __restrict__ hs, const float* __restrict__ wq,
             const float* __restrict__ wk, const float* __restrict__ wv)
{
    int i = blockIdx.x * 256 + threadIdx.x;
    if (i >= TOTA4) return;
    if (i < HS4)                        split4(hs, g_hsh, g_hsl, i);
    else if (i < HS4 + WQ4)             split4(wq, g_wqh, g_wql, i - HS4);
    else if (i < HS4 + WQ4 + WK4)       split4(wk, g_wkh, g_wkl, i - HS4 - WQ4);
    else                                split4(wv, g_wvh, g_wvl, i - HS4 - WQ4 - WK4);
}

__global__ __launch_bounds__(256)
void split_wo(const float* __restrict__ wo)
{
    int i = blockIdx.x * 256 + threadIdx.x;
    if (i >= WO4) return;
    split4(wo, g_woh, g_wol, i);
}

// ======== bf16x3 GEMM, 256x128 CTA, 16 warps (64x32 each), K-chunk 64 =====
// R12 config (best measured: 67.6% tensor) + warp phase skew.
#define LDB2    144
#define OFF_AH  0
#define OFF_AL  (256 * LDB2)
#define OFF_BH  (2 * 256 * LDB2)
#define OFF_BL  (2 * 256 * LDB2 + 128 * LDB2)
#define STG_B   (2 * 256 * LDB2 + 2 * 128 * LDB2)   // 110592
#define GEMM_SMEM (2 * STG_B)                       // 221184

__device__ __forceinline__ void gemm_core(
    const __nv_bfloat16* __restrict__ Ah, const __nv_bfloat16* __restrict__ Al,
    const __nv_bfloat16* __restrict__ Bh, const __nv_bfloat16* __restrict__ Bl,
    float* __restrict__ C, int N, int K, int bm, int bn,
    int kbase, int nch, char* smem)
{
    const uint32_t sb = smem_to_u32(smem);
    const int tid  = threadIdx.x;
    const int lane = tid & 31, wid = tid >> 5;
    const int wm = wid & 3, wn = wid >> 2;      // 4x4 warp grid, 64x32 each

    float acc[4][4][4];
#pragma unroll
    for (int mi = 0; mi < 4; mi++)
#pragma unroll
        for (int ni = 0; ni < 4; ni++)
#pragma unroll
            for (int q = 0; q < 4; q++) acc[mi][ni][q] = 0.f;

    const int ldr = tid >> 3, seg = tid & 7;

    auto cp_stage = [&](int c, int stg) {
        const int k0 = kbase + c * 64;
        const uint32_t dbase = sb + stg * STG_B;
#pragma unroll
        for (int p = 0; p < 4; p++) {           // A: 256 rows (hi+lo)
            int r = ldr + p * 64;
            uint32_t doff = r * LDB2 + seg * 16;
            size_t goff = (size_t)(bm + r) * K + k0 + seg * 8;
            cp16(dbase + OFF_AH + doff, Ah + goff);
            cp16(dbase + OFF_AL + doff, Al + goff);
        }
#pragma unroll
        for (int p = 0; p < 2; p++) {           // B: 128 rows (hi+lo)
            int r = ldr + p * 64;
            uint32_t doff = r * LDB2 + seg * 16;
            size_t goff = (size_t)(bn + r) * K + k0 + seg * 8;
            cp16(dbase + OFF_BH + doff, Bh + goff);
            cp16(dbase + OFF_BL + doff, Bl + goff);
        }
        CP_COMMIT();
    };

    auto compute = [&](int stg) {
        const uint32_t base = sb + stg * STG_B;
        const int ksb = wn & 3;                 // per-SMSP phase skew
#pragma unroll
        for (int ks2 = 0; ks2 < 4; ks2++) {
            const int ks = (ks2 + ksb) & 3;
            uint32_t aH[4][4], aL[4][4];
            const uint32_t acol = (uint32_t)ks * 32 + (lane >> 4) * 16;
#pragma unroll
            for (int mi = 0; mi < 4; mi++) {
                uint32_t off = (uint32_t)(wm * 64 + mi * 16 + (lane & 15)) *
                               LDB2 + acol;
                ldsm4(aH[mi], base + OFF_AH + off);
                ldsm4(aL[mi], base + OFF_AL + off);
            }
            const uint32_t bcol = (uint32_t)ks * 32 + ((lane >> 3) & 1) * 16;
#pragma unroll
            for (int nt = 0; nt < 2; nt++) {
                int brow = wn * 32 + nt * 16 + (lane & 7) + ((lane >> 4) << 3);
                uint32_t off = (uint32_t)brow * LDB2 + bcol;
                uint32_t bh[4], bl[4];
                ldsm4(bh, base + OFF_BH + off);
                ldsm4(bl, base + OFF_BL + off);
#pragma unroll
                for (int mi = 0; mi < 4; mi++) {
                    mma_bf16(acc[mi][2 * nt],     aH[mi], bh[0], bh[1]);
                    mma_bf16(acc[mi][2 * nt],     aH[mi], bl[0], bl[1]);
                    mma_bf16(acc[mi][2 * nt],     aL[mi], bh[0], bh[1]);
                    mma_bf16(acc[mi][2 * nt + 1], aH[mi], bh[2], bh[3]);
                    mma_bf16(acc[mi][2 * nt + 1], aH[mi], bl[2], bl[3]);
                    mma_bf16(acc[mi][2 * nt + 1], aL[mi], bh[2], bh[3]);
                }
            }
        }
    };

    cp_stage(0, 0);
    cp_stage(1, 1);
    CP_WAIT1();
    __syncthreads();

    for (int c = 0; c < nch; c++) {
        compute(c & 1);
        if (c + 1 < nch) {
            __syncthreads();
            if (c + 2 < nch) { cp_stage(c + 2, c & 1); CP_WAIT1(); }
            else             { CP_WAIT0(); }
            __syncthreads();
        }
    }

    const int rbase = bm + wm * 64 + (lane >> 2);
    const int cbase = bn + wn * 32 + 2 * (lane & 3);
#pragma unroll
    for (int mi = 0; mi < 4; mi++)
#pragma unroll
        for (int ni = 0; ni < 4; ni++) {
            int r0 = rbase + mi * 16, cc = cbase + ni * 8;
            *(float2*)(C + (size_t)r0 * N + cc) =
                make_float2(acc[mi][ni][0], acc[mi][ni][1]);
            *(float2*)(C + (size_t)(r0 + 8) * N + cc) =
                make_float2(acc[mi][ni][2], acc[mi][ni][3]);
        }
}

// fused QKV, split-K=2: grid (32, 32); y -> (kh, mtile). 1024 CTAs.
__global__ __launch_bounds__(512, 1)
void qkv_gemm()
{
    extern __shared__ __align__(128) char smem[];
    const int bx = blockIdx.x;
    const int kh = blockIdx.y & 1;
    const int my = blockIdx.y >> 1;
    const __nv_bfloat16 *Bh, *Bl;
    float* C;
    int Nout, bn;
    if (bx < 16)      { Bh = g_wqh; Bl = g_wql; C = kh ? g_q2 : g_q; Nout = 2048; bn = bx * 128; }
    else if (bx < 24) { Bh = g_wkh; Bl = g_wkl; C = kh ? g_k2 : g_k; Nout = 1024; bn = (bx - 16) * 128; }
    else              { Bh = g_wvh; Bl = g_wvl; C = kh ? g_v2 : g_v; Nout = 1024; bn = (bx - 24) * 128; }
    gemm_core(g_hsh, g_hsl, Bh, Bl, C, Nout, HIDDEN, my * 256, bn,
              kh * 1024, 16, smem);
}

// O projection, split-K=4: grid (16, 64); y -> (kq, mtile). 1024 CTAs.
__global__ __launch_bounds__(512, 1)
void o_gemm()
{
    extern __shared__ __align__(128) char smem[];
    const int kq = blockIdx.y & 3;
    const int my = blockIdx.y >> 2;
    float* part[4];
    part[0] = g_q; part[1] = g_q2; part[2] = g_op2; part[3] = g_op3;
    gemm_core(g_aoh, g_aol, g_woh, g_wol, part[kq], HIDDEN, NHEAD * HDIM,
              my * 256, blockIdx.x * 128, kq * 512, 8, smem);
}

// sum 4 O partials -> out
__global__ __launch_bounds__(256)
void add4(float* __restrict__ out)
{
    int i = blockIdx.x * 256 + threadIdx.x;   // float4 index, n = 2097152
    float4 a = ((const float4*)g_q)[i];
    float4 b = ((const float4*)g_q2)[i];
    float4 c = ((const float4*)g_op2)[i];
    float4 d = ((const float4*)g_op3)[i];
    ((float4*)out)[i] = make_float4(a.x + b.x + c.x + d.x,
                                    a.y + b.y + c.y + d.y,
                                    a.z + b.z + c.z + d.z,
                                    a.w + b.w + c.w + d.w);
}

// ===================== RoPE table =========================================
__global__ void rope_table_kernel()
{
    int idx = blockIdx.x * 256 + threadIdx.x;
    if (idx >= SEQ * 64) return;
    int s = idx >> 6, f = idx & 63;
    double invf = pow(1.0e6, -(double)f / 64.0);
    float ang = (float)s * (float)invf;
    g_cos[idx] = (float)cos((double)ang);
    g_sin[idx] = (float)sin((double)ang);
}

// ======= per-(s,head) RMSNorm + RoPE on (X0+X1) -> bf16 hi/lo =============
__global__ __launch_bounds__(128)
void qk_norm_rope_split(const float* __restrict__ X0, const float* __restrict__ X1,
                        const float* __restrict__ W,
                        __nv_bfloat16* __restrict__ Xh, __nv_bfloat16* __restrict__ Xl,
                        int nh, float scale)
{
    const int s = blockIdx.x, hh = blockIdx.y, d = threadIdx.x;
    const size_t off = ((size_t)s * nh + hh) * HDIM + d;
    float v = X0[off] + X1[off];

    float ss = v * v;
#pragma unroll
    for (int o = 16; o > 0; o >>= 1) ss += __shfl_xor_sync(0xffffffffu, ss, o);
    __shared__ float wsum[4];
    __shared__ float sh[128];
    if ((d & 31) == 0) wsum[d >> 5] = ss;
    __syncthreads();
    float tot = wsum[0] + wsum[1] + wsum[2] + wsum[3];
    float r = rsqrtf(tot * (1.0f / 128.0f) + 1e-6f);
    v = v * r * W[d];

    sh[d] = v;
    __syncthreads();
    int f = d & 63;
    float c  = g_cos[s * 64 + f];
    float sn = g_sin[s * 64 + f];
    float o2 = sh[d ^ 64];
    float out = ((d < 64) ? (v * c - o2 * sn) : (v * c + o2 * sn)) * scale;

    __nv_bfloat16 hi = __float2bfloat16(out);
    Xh[off] = hi;
    Xl[off] = __float2bfloat16(out - __bfloat162float(hi));
}

// ==== V: (V0+V1) fp32 [s][kvh][d] -> bf16 hi/lo transposed [kvh][d][s] ====
__global__ __launch_bounds__(256)
void v_split_t(const float* __restrict__ V0, const float* __restrict__ V1,
               __nv_bfloat16* __restrict__ Vth, __nv_bfloat16* __restrict__ Vtl)
{
    __shared__ float t[32][33];
    const int s0 = blockIdx.x * 32, d0 = blockIdx.y * 32, kvh = blockIdx.z;
    const int x = threadIdx.x, y = threadIdx.y;
#pragma unroll
    for (int yy = y; yy < 32; yy += 8) {
        size_t g = (size_t)(s0 + yy) * (NKVH * HDIM) + kvh * HDIM + d0 + x;
        t[x][yy] = V0[g] + V1[g];
    }
    __syncthreads();
#pragma unroll
    for (int yy = y; yy < 32; yy += 8) {
        float v = t[yy][x];
        __nv_bfloat16 hi = __float2bfloat16(v);
        size_t o = (size_t)kvh * HDIM * SEQ + (size_t)(d0 + yy) * SEQ + s0 + x;
        Vth[o] = hi;
        Vtl[o] = __float2bfloat16(v - __bfloat162float(hi));
    }
}

// ===================== flash attention on mma.sync (validated) ============
#define SKQ 136
#define SKV 72
#define FLASH_SMEM ((4 * 64 * SKQ + 2 * 128 * SKV) * 2)

__global__ __launch_bounds__(128)
void flash_mma(const __nv_bfloat16* __restrict__ Qh, const __nv_bfloat16* __restrict__ Ql,
               const __nv_bfloat16* __restrict__ Kh, const __nv_bfloat16* __restrict__ Kl,
               const __nv_bfloat16* __restrict__ Vth, const __nv_bfloat16* __restrict__ Vtl,
               __nv_bfloat16* __restrict__ Oh, __nv_bfloat16* __restrict__ Ol)
{
    extern __shared__ __align__(128) __nv_bfloat16 fsm[];
    __nv_bfloat16* sQh = fsm;
    __nv_bfloat16* sQl = sQh + 64 * SKQ;
    __nv_bfloat16* sKh = sQl + 64 * SKQ;
    __nv_bfloat16* sKl = sKh + 64 * SKQ;
    __nv_bfloat16* sVh = sKl + 64 * SKQ;
    __nv_bfloat16* sVl = sVh + 128 * SKV;

    const uint32_t bQh = smem_to_u32(sQh), bQl = smem_to_u32(sQl);
    const uint32_t bKh = smem_to_u32(sKh), bKl = smem_to_u32(sKl);
    const uint32_t bVh = smem_to_u32(sVh), bVl = smem_to_u32(sVl);

    const int h = blockIdx.y, kvh = h >> 1;
    const int qi = (int)gridDim.x - 1 - (int)blockIdx.x;
    const int tid = threadIdx.x, lane = tid & 31, warp = tid >> 5;

#pragma unroll
    for (int i = tid; i < 1024; i += 128) {
        int r = i >> 4, c = i & 15;
        size_t g = (size_t)(qi * 64 + r) * (NHEAD * HDIM) + h * HDIM + c * 8;
        *(uint4*)(sQh + r * SKQ + c * 8) = *(const uint4*)(Qh + g);
        *(uint4*)(sQl + r * SKQ + c * 8) = *(const uint4*)(Ql + g);
    }

    float o[16][4];
#pragma unroll
    for (int t = 0; t < 16; t++)
#pragma unroll
        for (int q = 0; q < 4; q++) o[t][q] = 0.f;
    float m0 = -1e30f, m1 = -1e30f, l0 = 0.f, l1 = 0.f;

    for (int j = 0; j <= qi; j++) {
        __syncthreads();
#pragma unroll
        for (int i = tid; i < 1024; i += 128) {
            int r = i >> 4, c = i & 15;
            size_t g = (size_t)(j * 64 + r) * (NKVH * HDIM) + kvh * HDIM + c * 8;
            *(uint4*)(sKh + r * SKQ + c * 8) = *(const uint4*)(Kh + g);
            *(uint4*)(sKl + r * SKQ + c * 8) = *(const uint4*)(Kl + g);
        }
#pragma unroll
        for (int i = tid; i < 1024; i += 128) {
            int r = i >> 3, c = i & 7;
            size_t g = (size_t)kvh * HDIM * SEQ + (size_t)r * SEQ + j * 64 + c * 8;
            *(uint4*)(sVh + r * SKV + c * 8) = *(const uint4*)(Vth + g);
            *(uint4*)(sVl + r * SKV + c * 8) = *(const uint4*)(Vtl + g);
        }
        __syncthreads();

        float s[8][4];
#pragma unroll
        for (int t = 0; t < 8; t++)
#pragma unroll
            for (int q = 0; q < 4; q++) s[t][q] = 0.f;

#pragma unroll
        for (int u = 0; u < 8; u++) {
            uint32_t aH[4], aL[4];
            uint32_t qoff = (uint32_t)(warp * 16 + (lane & 15)) * (SKQ * 2) +
                            u * 32 + (lane >> 4) * 16;
            ldsm4(aH, bQh + qoff);
            ldsm4(aL, bQl + qoff);
#pragma unroll
            for (int g = 0; g < 4; g++) {
                uint32_t koff = (uint32_t)(g * 16 + (lane & 7) + ((lane >> 4) << 3)) *
                                (SKQ * 2) + u * 32 + ((lane >> 3) & 1) * 16;
                uint32_t bh[4], bl[4];
                ldsm4(bh, bKh + koff);
                ldsm4(bl, bKl + koff);
                mma_bf16(s[2 * g],     aH, bh[0], bh[1]);
                mma_bf16(s[2 * g],     aH, bl[0], bl[1]);
                mma_bf16(s[2 * g],     aL, bh[0], bh[1]);
                mma_bf16(s[2 * g + 1], aH, bh[2], bh[3]);
                mma_bf16(s[2 * g + 1], aH, bl[2], bl[3]);
                mma_bf16(s[2 * g + 1], aL, bh[2], bh[3]);
            }
        }

        if (j == qi) {
            int lr = warp * 16 + (lane >> 2);
#pragma unroll
            for (int t = 0; t < 8; t++) {
                int c0 = 8 * t + 2 * (lane & 3);
                if (c0 > lr)          s[t][0] = -1e30f;
                if (c0 + 1 > lr)      s[t][1] = -1e30f;
                if (c0 > lr + 8)      s[t][2] = -1e30f;
                if (c0 + 1 > lr + 8)  s[t][3] = -1e30f;
            }
        }
        float mx0 = m0, mx1 = m1;
#pragma unroll
        for (int t = 0; t < 8; t++) {
            mx0 = fmaxf(mx0, fmaxf(s[t][0], s[t][1]));
            mx1 = fmaxf(mx1, fmaxf(s[t][2], s[t][3]));
        }
        mx0 = fmaxf(mx0, __shfl_xor_sync(0xffffffffu, mx0, 1));
        mx0 = fmaxf(mx0, __shfl_xor_sync(0xffffffffu, mx0, 2));
        mx1 = fmaxf(mx1, __shfl_xor_sync(0xffffffffu, mx1, 1));
        mx1 = fmaxf(mx1, __shfl_xor_sync(0xffffffffu, mx1, 2));

        float a0 = __expf(m0 - mx0), a1 = __expf(m1 - mx1);
        m0 = mx0; m1 = mx1;

        float rs0 = 0.f, rs1 = 0.f;
        uint32_t pH[4][4], pL[4][4];
#pragma unroll
        for (int t = 0; t < 8; t++) {
            float p0 = __expf(s[t][0] - mx0), p1 = __expf(s[t][1] - mx0);
            float p2 = __expf(s[t][2] - mx1), p3 = __expf(s[t][3] - mx1);
            rs0 += p0 + p1; rs1 += p2 + p3;
            float h0 = __bfloat162float(__float2bfloat16(p0));
            float h1 = __bfloat162float(__float2bfloat16(p1));
            float h2 = __bfloat162float(__float2bfloat16(p2));
            float h3 = __bfloat162float(__float2bfloat16(p3));
            int u = t >> 1, e = (t & 1) * 2;
            pH[u][e]     = pack_bf16(h0, h1);
            pH[u][e + 1] = pack_bf16(h2, h3);
            pL[u][e]     = pack_bf16(p0 - h0, p1 - h1);
            pL[u][e + 1] = pack_bf16(p2 - h2, p3 - h3);
        }
        rs0 += __shfl_xor_sync(0xffffffffu, rs0, 1);
        rs0 += __shfl_xor_sync(0xffffffffu, rs0, 2);
        rs1 += __shfl_xor_sync(0xffffffffu, rs1, 1);
        rs1 += __shfl_xor_sync(0xffffffffu, rs1, 2);
        l0 = l0 * a0 + rs0;
        l1 = l1 * a1 + rs1;
#pragma unroll
        for (int t = 0; t < 16; t++) {
            o[t][0] *= a0; o[t][1] *= a0; o[t][2] *= a1; o[t][3] *= a1;
        }

#pragma unroll
        for (int u = 0; u < 4; u++) {
#pragma unroll
            for (int g = 0; g < 8; g++) {
                uint32_t voff = (uint32_t)(g * 16 + (lane & 7) + ((lane >> 4) << 3)) *
                                (SKV * 2) + u * 32 + ((lane >> 3) & 1) * 16;
                uint32_t bh[4], bl[4];
                ldsm4(bh, bVh + voff);
                ldsm4(bl, bVl + voff);
                mma_bf16(o[2 * g],     pH[u], bh[0], bh[1]);
                mma_bf16(o[2 * g],     pH[u], bl[0], bl[1]);
                mma_bf16(o[2 * g],     pL[u], bh[0], bh[1]);
                mma_bf16(o[2 * g + 1], pH[u], bh[2], bh[3]);
                mma_bf16(o[2 * g + 1], pH[u], bl[2], bl[3]);
                mma_bf16(o[2 * g + 1], pL[u], bh[2], bh[3]);
            }
        }
    }

    float inv0 = 1.f / l0, inv1 = 1.f / l1;
    int r = qi * 64 + warp * 16 + (lane >> 2);
#pragma unroll
    for (int t = 0; t < 16; t++) {
        int d = 8 * t + 2 * (lane & 3);
        size_t o0 = (size_t)r * (NHEAD * HDIM) + h * HDIM + d;
        size_t o1 = (size_t)(r + 8) * (NHEAD * HDIM) + h * HDIM + d;
        float v0 = o[t][0] * inv0, v1 = o[t][1] * inv0;
        float v2 = o[t][2] * inv1, v3 = o[t][3] * inv1;
        float h0 = __bfloat162float(__float2bfloat16(v0));
        float h1 = __bfloat162float(__float2bfloat16(v1));
        float h2 = __bfloat162float(__float2bfloat16(v2));
        float h3 = __bfloat162float(__float2bfloat16(v3));
        *(uint32_t*)(Oh + o0) = pack_bf16(h0, h1);
        *(uint32_t*)(Ol + o0) = pack_bf16(v0 - h0, v1 - h1);
        *(uint32_t*)(Oh + o1) = pack_bf16(h2, h3);
        *(uint32_t*)(Ol + o1) = pack_bf16(v2 - h2, v3 - h3);
    }
}

// ===========================================================================
extern "C" void kernel_launch(void* const* d_in, const int* in_sizes, int n_in,
                              void* d_out, int out_size)
{
    const float* hs  = (const float*)d_in[0];
    const float* wq  = (const float*)d_in[2];
    const float* wk  = (const float*)d_in[3];
    const float* wv  = (const float*)d_in[4];
    const float* wo  = (const float*)d_in[5];
    const float* qnw = (const float*)d_in[6];
    const float* knw = (const float*)d_in[7];
    float* out = (float*)d_out;

    float *gq, *gq2, *gk, *gk2, *gv, *gv2;
    cudaGetSymbolAddress((void**)&gq,  g_q);  cudaGetSymbolAddress((void**)&gq2, g_q2);
    cudaGetSymbolAddress((void**)&gk,  g_k);  cudaGetSymbolAddress((void**)&gk2, g_k2);
    cudaGetSymbolAddress((void**)&gv,  g_v);  cudaGetSymbolAddress((void**)&gv2, g_v2);

    __nv_bfloat16 *aoh, *aol, *qh2, *ql2, *kh2, *kl2, *vth, *vtl;
    cudaGetSymbolAddress((void**)&aoh, g_aoh); cudaGetSymbolAddress((void**)&aol, g_aol);
    cudaGetSymbolAddress((void**)&qh2, g_qh2); cudaGetSymbolAddress((void**)&ql2, g_ql2);
    cudaGetSymbolAddress((void**)&kh2, g_kh2); cudaGetSymbolAddress((void**)&kl2, g_kl2);
    cudaGetSymbolAddress((void**)&vth, g_vth); cudaGetSymbolAddress((void**)&vtl, g_vtl);

    cudaFuncSetAttribute(qkv_gemm,
                         cudaFuncAttributeMaxDynamicSharedMemorySize, GEMM_SMEM);
    cudaFuncSetAttribute(o_gemm,
                         cudaFuncAttributeMaxDynamicSharedMemorySize, GEMM_SMEM);
    cudaFuncSetAttribute(flash_mma,
                         cudaFuncAttributeMaxDynamicSharedMemorySize, FLASH_SMEM);

    // 1. RoPE table
    rope_table_kernel<<<SEQ * 64 / 256, 256>>>();
    // 2. split hs + wq + wk + wv
    split_a<<<TOTA4 / 256, 256>>>(hs, wq, wk, wv);
    // 3. split wo
    split_wo<<<WO4 / 256, 256>>>(wo);
    // 4. fused QKV projection, split-K=2 (R12 config)  <- ncu capture slot
    qkv_gemm<<<dim3(32, 32), 512, GEMM_SMEM>>>();
    // 5-7. RMSNorm+RoPE on summed partials -> bf16 operands; V transpose+split
    qk_norm_rope_split<<<dim3(SEQ, NHEAD), 128>>>(gq, gq2, qnw, qh2, ql2, NHEAD,
                                                  0.08838834764831845f);
    qk_norm_rope_split<<<dim3(SEQ, NKVH), 128>>>(gk, gk2, knw, kh2, kl2, NKVH, 1.0f);
    v_split_t<<<dim3(SEQ / 32, HDIM / 32, NKVH), dim3(32, 8)>>>(gv, gv2, vth, vtl);
    // 8. flash attention -> bf16 hi/lo AO
    flash_mma<<<dim3(SEQ / 64, NHEAD), 128, FLASH_SMEM>>>(qh2, ql2, kh2, kl2,
                                                          vth, vtl, aoh, aol);
    // 9. O projection, split-K=4 into partials (reuses g_q/g_q2 + g_op2/g_op3)
    o_gemm<<<dim3(16, 64), 512, GEMM_SMEM>>>();
    // 10. sum partials -> out
    add4<<<SEQ * HIDDEN / 1024, 256>>>(out);
}

// round 16
// speedup vs baseline: 1.0259x; 1.0133x over previous
#include <cuda_runtime.h>
#include <cuda_bf16.h>
#include <math.h>
#include <cstdint>

#define SEQ    4096
#define HIDDEN 2048
#define NHEAD  16
#define NKVH   8
#define HDIM   128

// ===================== helpers ============================================
__device__ __forceinline__ uint32_t smem_to_u32(const void* p) {
    uint32_t a;
    asm("{ .reg .u64 t; cvta.to.shared.u64 t, %1; cvt.u32.u64 %0, t; }"
        : "=r"(a) : "l"(p));
    return a;
}
__device__ __forceinline__ void ldsm4(uint32_t* r, uint32_t addr) {
    asm volatile("ldmatrix.sync.aligned.m8n8.x4.shared.b16 {%0,%1,%2,%3}, [%4];"
        : "=r"(r[0]), "=r"(r[1]), "=r"(r[2]), "=r"(r[3]) : "r"(addr));
}
__device__ __forceinline__ void mma_bf16(float* c, const uint32_t* a,
                                         uint32_t b0, uint32_t b1) {
    asm volatile(
        "mma.sync.aligned.m16n8k16.row.col.f32.bf16.bf16.f32 "
        "{%0,%1,%2,%3}, {%4,%5,%6,%7}, {%8,%9}, {%0,%1,%2,%3};"
        : "+f"(c[0]), "+f"(c[1]), "+f"(c[2]), "+f"(c[3])
        : "r"(a[0]), "r"(a[1]), "r"(a[2]), "r"(a[3]), "r"(b0), "r"(b1));
}
__device__ __forceinline__ uint32_t pack_bf16(float x, float y) {
    __nv_bfloat162 t;
    t.x = __float2bfloat16(x); t.y = __float2bfloat16(y);
    return *(uint32_t*)&t;
}
__device__ __forceinline__ void cp16(uint32_t dst, const void* src) {
    asm volatile("cp.async.cg.shared.global [%0], [%1], 16;"
                 :: "r"(dst), "l"(src));
}
#define CP_COMMIT() asm volatile("cp.async.commit_group;" ::: "memory")
#define CP_WAIT1()  asm volatile("cp.async.wait_group 1;" ::: "memory")
#define CP_WAIT0()  asm volatile("cp.async.wait_group 0;" ::: "memory")

// ===================== scratch (static device globals) ====================
__device__ float g_q  [SEQ * NHEAD * HDIM];   // QKV partial 0 / O partial 0
__device__ float g_q2 [SEQ * NHEAD * HDIM];   // QKV partial 1 / O partial 1
__device__ float g_op2[SEQ * NHEAD * HDIM];   // O partial 2
__device__ float g_op3[SEQ * NHEAD * HDIM];   // O partial 3
__device__ float g_k  [SEQ * NKVH  * HDIM];
__device__ float g_k2 [SEQ * NKVH  * HDIM];
__device__ float g_v  [SEQ * NKVH  * HDIM];
__device__ float g_v2 [SEQ * NKVH  * HDIM];
__device__ float g_cos[SEQ * 64];
__device__ float g_sin[SEQ * 64];

__device__ __nv_bfloat16 g_hsh[SEQ * HIDDEN],          g_hsl[SEQ * HIDDEN];
__device__ __nv_bfloat16 g_wqh[NHEAD * HDIM * HIDDEN], g_wql[NHEAD * HDIM * HIDDEN];
__device__ __nv_bfloat16 g_wkh[NKVH * HDIM * HIDDEN],  g_wkl[NKVH * HDIM * HIDDEN];
__device__ __nv_bfloat16 g_wvh[NKVH * HDIM * HIDDEN],  g_wvl[NKVH * HDIM * HIDDEN];
__device__ __nv_bfloat16 g_woh[HIDDEN * NHEAD * HDIM], g_wol[HIDDEN * NHEAD * HDIM];
__device__ __nv_bfloat16 g_aoh[SEQ * NHEAD * HDIM],    g_aol[SEQ * NHEAD * HDIM];

__device__ __nv_bfloat16 g_qh2[SEQ * NHEAD * HDIM], g_ql2[SEQ * NHEAD * HDIM];
__device__ __nv_bfloat16 g_kh2[SEQ * NKVH * HDIM],  g_kl2[SEQ * NKVH * HDIM];
__device__ __nv_bfloat16 g_vth[NKVH * HDIM * SEQ],  g_vtl[NKVH * HDIM * SEQ];

// ===================== fp32 -> bf16 hi/lo splits ==========================
#define HS4 2097152
#define WQ4 1048576
#define WK4 524288
#define WV4 524288
#define WO4 1048576
#define TOTA4 (HS4 + WQ4 + WK4 + WV4)

__device__ __forceinline__ void split4(const float* __restrict__ x,
                                       __nv_bfloat16* __restrict__ h,
                                       __nv_bfloat16* __restrict__ l, int j)
{
    float4 v = ((const float4*)x)[j];
    __nv_bfloat16 h0 = __float2bfloat16(v.x);
    __nv_bfloat16 h1 = __float2bfloat16(v.y);
    __nv_bfloat16 h2 = __float2bfloat16(v.z);
    __nv_bfloat16 h3 = __float2bfloat16(v.w);
    __nv_bfloat16 l0 = __float2bfloat16(v.x - __bfloat162float(h0));
    __nv_bfloat16 l1 = __float2bfloat16(v.y - __bfloat162float(h1));
    __nv_bfloat16 l2 = __float2bfloat16(v.z - __bfloat162float(h2));
    __nv_bfloat16 l3 = __float2bfloat16(v.w - __bfloat162float(h3));
    ushort4 hv = make_ushort4(__bfloat16_as_ushort(h0), __bfloat16_as_ushort(h1),
                              __bfloat16_as_ushort(h2), __bfloat16_as_ushort(h3));
    ushort4 lv = make_ushort4(__bfloat16_as_ushort(l0), __bfloat16_as_ushort(l1),
                              __bfloat16_as_ushort(l2), __bfloat16_as_ushort(l3));
    *(ushort4*)(h + 4 * (size_t)j) = hv;
    *(ushort4*)(l + 4 * (size_t)j) = lv;
}

__global__ __launch_bounds__(256)
void split_a(const float* __restrict__ hs, const float* __restrict__ wq,
             const float* __restrict__ wk, const float* __restrict__ wv)
{
    int i = blockIdx.x * 256 + threadIdx.x;
    if (i >= TOTA4) return;
    if (i < HS4)                        split4(hs, g_hsh, g_hsl, i);
    else if (i < HS4 + WQ4)             split4(wq, g_wqh, g_wql, i - HS4);
    else if (i < HS4 + WQ4 + WK4)       split4(wk, g_wkh, g_wkl, i - HS4 - WQ4);
    else                                split4(wv, g_wvh, g_wvl, i - HS4 - WQ4 - WK4);
}

__global__ __launch_bounds__(256)
void split_wo(const float* __restrict__ wo)
{
    int i = blockIdx.x * 256 + threadIdx.x;
    if (i >= WO4) return;
    split4(wo, g_woh, g_wol, i);
}

// == bf16x3 GEMM, 256x128 CTA, 8 warps (64x64 each), K-chunk 64, =========
// == register-level fragment double-buffering (ldsm/MMA overlap) =========
#define LDB2    144
#define OFF_AH  0
#define OFF_AL  (256 * LDB2)
#define OFF_BH  (2 * 256 * LDB2)
#define OFF_BL  (2 * 256 * LDB2 + 128 * LDB2)
#define STG_B   (2 * 256 * LDB2 + 2 * 128 * LDB2)   // 110592
#define GEMM_SMEM (2 * STG_B)                       // 221184

__device__ __forceinline__ void gemm_core(
    const __nv_bfloat16* __restrict__ Ah, const __nv_bfloat16* __restrict__ Al,
    const __nv_bfloat16* __restrict__ Bh, const __nv_bfloat16* __restrict__ Bl,
    float* __restrict__ C, int N, int K, int bm, int bn,
    int kbase, int nch, char* smem)
{
    const uint32_t sb = smem_to_u32(smem);
    const int tid  = threadIdx.x;
    const int lane = tid & 31, wid = tid >> 5;
    const int wm = wid & 3, wn2 = wid >> 2;     // 4x2 warp grid, 64x64 each

    float acc[4][8][4];
#pragma unroll
    for (int mi = 0; mi < 4; mi++)
#pragma unroll
        for (int ni = 0; ni < 8; ni++)
#pragma unroll
            for (int q = 0; q < 4; q++) acc[mi][ni][q] = 0.f;

    const int ldr = tid >> 3, seg = tid & 7;    // 256 threads

    auto cp_stage = [&](int c, int stg) {
        const int k0 = kbase + c * 64;
        const uint32_t dbase = sb + stg * STG_B;
#pragma unroll
        for (int p = 0; p < 8; p++) {           // A: 256 rows (hi+lo)
            int r = ldr + p * 32;
            uint32_t doff = r * LDB2 + seg * 16;
            size_t goff = (size_t)(bm + r) * K + k0 + seg * 8;
            cp16(dbase + OFF_AH + doff, Ah + goff);
            cp16(dbase + OFF_AL + doff, Al + goff);
        }
#pragma unroll
        for (int p = 0; p < 4; p++) {           // B: 128 rows (hi+lo)
            int r = ldr + p * 32;
            uint32_t doff = r * LDB2 + seg * 16;
            size_t goff = (size_t)(bn + r) * K + k0 + seg * 8;
            cp16(dbase + OFF_BH + doff, Bh + goff);
            cp16(dbase + OFF_BL + doff, Bl + goff);
        }
        CP_COMMIT();
    };

    // fragment double buffers
    uint32_t aH[2][4][4], aL[2][4][4];   // A: [slot][mi][reg]
    uint32_t bh[2][4], bl[2][4];         // B: [slot][reg]

    auto load_A = [&](uint32_t base, int ks, int sl) {
        const uint32_t acol = (uint32_t)ks * 32 + (lane >> 4) * 16;
#pragma unroll
        for (int mi = 0; mi < 4; mi++) {
            uint32_t off = (uint32_t)(wm * 64 + mi * 16 + (lane & 15)) * LDB2 + acol;
            ldsm4(aH[sl][mi], base + OFF_AH + off);
            ldsm4(aL[sl][mi], base + OFF_AL + off);
        }
    };
    auto load_B = [&](uint32_t base, int ks, int nt, int sl) {
        const uint32_t bcol = (uint32_t)ks * 32 + ((lane >> 3) & 1) * 16;
        int brow = wn2 * 64 + nt * 16 + (lane & 7) + ((lane >> 4) << 3);
        uint32_t off = (uint32_t)brow * LDB2 + bcol;
        ldsm4(bh[sl], base + OFF_BH + off);
        ldsm4(bl[sl], base + OFF_BL + off);
    };
    auto mma_step = [&](int asl, int bsl, int nt) {
#pragma unroll
        for (int mi = 0; mi < 4; mi++) {
            mma_bf16(acc[mi][2 * nt],     aH[asl][mi], bh[bsl][0], bh[bsl][1]);
            mma_bf16(acc[mi][2 * nt],     aH[asl][mi], bl[bsl][0], bl[bsl][1]);
            mma_bf16(acc[mi][2 * nt],     aL[asl][mi], bh[bsl][0], bh[bsl][1]);
            mma_bf16(acc[mi][2 * nt + 1], aH[asl][mi], bh[bsl][2], bh[bsl][3]);
            mma_bf16(acc[mi][2 * nt + 1], aH[asl][mi], bl[bsl][2], bl[bsl][3]);
            mma_bf16(acc[mi][2 * nt + 1], aL[asl][mi], bh[bsl][2], bh[bsl][3]);
        }
    };

    auto compute = [&](int stg) {
        const uint32_t base = sb + stg * STG_B;
        load_A(base, 0, 0);
        load_B(base, 0, 0, 0);
#pragma unroll
        for (int ks = 0; ks < 4; ks++) {
            const int asl = ks & 1;
#pragma unroll
            for (int nt = 0; nt < 4; nt++) {
                const int bsl = (ks * 4 + nt) & 1;
                if (nt < 3) {
                    load_B(base, ks, nt + 1, bsl ^ 1);        // prefetch next B
                } else if (ks < 3) {
                    load_A(base, ks + 1, asl ^ 1);            // prefetch next A
                    load_B(base, ks + 1, 0, bsl ^ 1);
                }
                mma_step(asl, bsl, nt);
            }
        }
    };

    cp_stage(0, 0);
    cp_stage(1, 1);
    CP_WAIT1();
    __syncthreads();

    for (int c = 0; c < nch; c++) {
        compute(c & 1);
        if (c + 1 < nch) {
            __syncthreads();
            if (c + 2 < nch) { cp_stage(c + 2, c & 1); CP_WAIT1(); }
            else             { CP_WAIT0(); }
            __syncthreads();
        }
    }

    const int rbase = bm + wm * 64 + (lane >> 2);
    const int cbase = bn + wn2 * 64 + 2 * (lane & 3);
#pragma unroll
    for (int mi = 0; mi < 4; mi++)
#pragma unroll
        for (int ni = 0; ni < 8; ni++) {
            int r0 = rbase + mi * 16, cc = cbase + ni * 8;
            *(float2*)(C + (size_t)r0 * N + cc) =
                make_float2(acc[mi][ni][0], acc[mi][ni][1]);
            *(float2*)(C + (size_t)(r0 + 8) * N + cc) =
                make_float2(acc[mi][ni][2], acc[mi][ni][3]);
        }
}

// fused QKV, split-K=2: grid (32, 32); y -> (kh, mtile). 1024 CTAs.
__global__ __launch_bounds__(256, 1)
void qkv_gemm()
{
    extern __shared__ __align__(128) char smem[];
    const int bx = blockIdx.x;
    const int kh = blockIdx.y & 1;
    const int my = blockIdx.y >> 1;
    const __nv_bfloat16 *Bh, *Bl;
    float* C;
    int Nout, bn;
    if (bx < 16)      { Bh = g_wqh; Bl = g_wql; C = kh ? g_q2 : g_q; Nout = 2048; bn = bx * 128; }
    else if (bx < 24) { Bh = g_wkh; Bl = g_wkl; C = kh ? g_k2 : g_k; Nout = 1024; bn = (bx - 16) * 128; }
    else              { Bh = g_wvh; Bl = g_wvl; C = kh ? g_v2 : g_v; Nout = 1024; bn = (bx - 24) * 128; }
    gemm_core(g_hsh, g_hsl, Bh, Bl, C, Nout, HIDDEN, my * 256, bn,
              kh * 1024, 16, smem);
}

// O projection, split-K=4: grid (16, 64); y -> (kq, mtile). 1024 CTAs.
__global__ __launch_bounds__(256, 1)
void o_gemm()
{
    extern __shared__ __align__(128) char smem[];
    const int kq = blockIdx.y & 3;
    const int my = blockIdx.y >> 2;
    float* part[4];
    part[0] = g_q; part[1] = g_q2; part[2] = g_op2; part[3] = g_op3;
    gemm_core(g_aoh, g_aol, g_woh, g_wol, part[kq], HIDDEN, NHEAD * HDIM,
              my * 256, blockIdx.x * 128, kq * 512, 8, smem);
}

// sum 4 O partials -> out
__global__ __launch_bounds__(256)
void add4(float* __restrict__ out)
{
    int i = blockIdx.x * 256 + threadIdx.x;   // float4 index, n = 2097152
    float4 a = ((const float4*)g_q)[i];
    float4 b = ((const float4*)g_q2)[i];
    float4 c = ((const float4*)g_op2)[i];
    float4 d = ((const float4*)g_op3)[i];
    ((float4*)out)[i] = make_float4(a.x + b.x + c.x + d.x,
                                    a.y + b.y + c.y + d.y,
                                    a.z + b.z + c.z + d.z,
                                    a.w + b.w + c.w + d.w);
}

// ===================== RoPE table =========================================
__global__ void rope_table_kernel()
{
    int idx = blockIdx.x * 256 + threadIdx.x;
    if (idx >= SEQ * 64) return;
    int s = idx >> 6, f = idx & 63;
    double invf = pow(1.0e6, -(double)f / 64.0);
    float ang = (float)s * (float)invf;
    g_cos[idx] = (float)cos((double)ang);
    g_sin[idx] = (float)sin((double)ang);
}

// ======= per-(s,head) RMSNorm + RoPE on (X0+X1) -> bf16 hi/lo =============
__global__ __launch_bounds__(128)
void qk_norm_rope_split(const float* __restrict__ X0, const float* __restrict__ X1,
                        const float* __restrict__ W,
                        __nv_bfloat16* __restrict__ Xh, __nv_bfloat16* __restrict__ Xl,
                        int nh, float scale)
{
    const int s = blockIdx.x, hh = blockIdx.y, d = threadIdx.x;
    const size_t off = ((size_t)s * nh + hh) * HDIM + d;
    float v = X0[off] + X1[off];

    float ss = v * v;
#pragma unroll
    for (int o = 16; o > 0; o >>= 1) ss += __shfl_xor_sync(0xffffffffu, ss, o);
    __shared__ float wsum[4];
    __shared__ float sh[128];
    if ((d & 31) == 0) wsum[d >> 5] = ss;
    __syncthreads();
    float tot = wsum[0] + wsum[1] + wsum[2] + wsum[3];
    float r = rsqrtf(tot * (1.0f / 128.0f) + 1e-6f);
    v = v * r * W[d];

    sh[d] = v;
    __syncthreads();
    int f = d & 63;
    float c  = g_cos[s * 64 + f];
    float sn = g_sin[s * 64 + f];
    float o2 = sh[d ^ 64];
    float out = ((d < 64) ? (v * c - o2 * sn) : (v * c + o2 * sn)) * scale;

    __nv_bfloat16 hi = __float2bfloat16(out);
    Xh[off] = hi;
    Xl[off] = __float2bfloat16(out - __bfloat162float(hi));
}

// ==== V: (V0+V1) fp32 [s][kvh][d] -> bf16 hi/lo transposed [kvh][d][s] ====
__global__ __launch_bounds__(256)
void v_split_t(const float* __restrict__ V0, const float* __restrict__ V1,
               __nv_bfloat16* __restrict__ Vth, __nv_bfloat16* __restrict__ Vtl)
{
    __shared__ float t[32][33];
    const int s0 = blockIdx.x * 32, d0 = blockIdx.y * 32, kvh = blockIdx.z;
    const int x = threadIdx.x, y = threadIdx.y;
#pragma unroll
    for (int yy = y; yy < 32; yy += 8) {
        size_t g = (size_t)(s0 + yy) * (NKVH * HDIM) + kvh * HDIM + d0 + x;
        t[x][yy] = V0[g] + V1[g];
    }
    __syncthreads();
#pragma unroll
    for (int yy = y; yy < 32; yy += 8) {
        float v = t[yy][x];
        __nv_bfloat16 hi = __float2bfloat16(v);
        size_t o = (size_t)kvh * HDIM * SEQ + (size_t)(d0 + yy) * SEQ + s0 + x;
        Vth[o] = hi;
        Vtl[o] = __float2bfloat16(v - __bfloat162float(hi));
    }
}

// ===================== flash attention on mma.sync (validated) ============
#define SKQ 136
#define SKV 72
#define FLASH_SMEM ((4 * 64 * SKQ + 2 * 128 * SKV) * 2)

__global__ __launch_bounds__(128)
void flash_mma(const __nv_bfloat16* __restrict__ Qh, const __nv_bfloat16* __restrict__ Ql,
               const __nv_bfloat16* __restrict__ Kh, const __nv_bfloat16* __restrict__ Kl,
               const __nv_bfloat16* __restrict__ Vth, const __nv_bfloat16* __restrict__ Vtl,
               __nv_bfloat16* __restrict__ Oh, __nv_bfloat16* __restrict__ Ol)
{
    extern __shared__ __align__(128) __nv_bfloat16 fsm[];
    __nv_bfloat16* sQh = fsm;
    __nv_bfloat16* sQl = sQh + 64 * SKQ;
    __nv_bfloat16* sKh = sQl + 64 * SKQ;
    __nv_bfloat16* sKl = sKh + 64 * SKQ;
    __nv_bfloat16* sVh = sKl + 64 * SKQ;
    __nv_bfloat16* sVl = sVh + 128 * SKV;

    const uint32_t bQh = smem_to_u32(sQh), bQl = smem_to_u32(sQl);
    const uint32_t bKh = smem_to_u32(sKh), bKl = smem_to_u32(sKl);
    const uint32_t bVh = smem_to_u32(sVh), bVl = smem_to_u32(sVl);

    const int h = blockIdx.y, kvh = h >> 1;
    const int qi = (int)gridDim.x - 1 - (int)blockIdx.x;
    const int tid = threadIdx.x, lane = tid & 31, warp = tid >> 5;

#pragma unroll
    for (int i = tid; i < 1024; i += 128) {
        int r = i >> 4, c = i & 15;
        size_t g = (size_t)(qi * 64 + r) * (NHEAD * HDIM) + h * HDIM + c * 8;
        *(uint4*)(sQh + r * SKQ + c * 8) = *(const uint4*)(Qh + g);
        *(uint4*)(sQl + r * SKQ + c * 8) = *(const uint4*)(Ql + g);
    }

    float o[16][4];
#pragma unroll
    for (int t = 0; t < 16; t++)
#pragma unroll
        for (int q = 0; q < 4; q++) o[t][q] = 0.f;
    float m0 = -1e30f, m1 = -1e30f, l0 = 0.f, l1 = 0.f;

    for (int j = 0; j <= qi; j++) {
        __syncthreads();
#pragma unroll
        for (int i = tid; i < 1024; i += 128) {
            int r = i >> 4, c = i & 15;
            size_t g = (size_t)(j * 64 + r) * (NKVH * HDIM) + kvh * HDIM + c * 8;
            *(uint4*)(sKh + r * SKQ + c * 8) = *(const uint4*)(Kh + g);
            *(uint4*)(sKl + r * SKQ + c * 8) = *(const uint4*)(Kl + g);
        }
#pragma unroll
        for (int i = tid; i < 1024; i += 128) {
            int r = i >> 3, c = i & 7;
            size_t g = (size_t)kvh * HDIM * SEQ + (size_t)r * SEQ + j * 64 + c * 8;
            *(uint4*)(sVh + r * SKV + c * 8) = *(const uint4*)(Vth + g);
            *(uint4*)(sVl + r * SKV + c * 8) = *(const uint4*)(Vtl + g);
        }
        __syncthreads();

        float s[8][4];
#pragma unroll
        for (int t = 0; t < 8; t++)
#pragma unroll
            for (int q = 0; q < 4; q++) s[t][q] = 0.f;

#pragma unroll
        for (int u = 0; u < 8; u++) {
            uint32_t aH[4], aL[4];
            uint32_t qoff = (uint32_t)(warp * 16 + (lane & 15)) * (SKQ * 2) +
                            u * 32 + (lane >> 4) * 16;
            ldsm4(aH, bQh + qoff);
            ldsm4(aL, bQl + qoff);
#pragma unroll
            for (int g = 0; g < 4; g++) {
                uint32_t koff = (uint32_t)(g * 16 + (lane & 7) + ((lane >> 4) << 3)) *
                                (SKQ * 2) + u * 32 + ((lane >> 3) & 1) * 16;
                uint32_t bh[4], bl[4];
                ldsm4(bh, bKh + koff);
                ldsm4(bl, bKl + koff);
                mma_bf16(s[2 * g],     aH, bh[0], bh[1]);
                mma_bf16(s[2 * g],     aH, bl[0], bl[1]);
                mma_bf16(s[2 * g],     aL, bh[0], bh[1]);
                mma_bf16(s[2 * g + 1], aH, bh[2], bh[3]);
                mma_bf16(s[2 * g + 1], aH, bl[2], bl[3]);
                mma_bf16(s[2 * g + 1], aL, bh[2], bh[3]);
            }
        }

        if (j == qi) {
            int lr = warp * 16 + (lane >> 2);
#pragma unroll
            for (int t = 0; t < 8; t++) {
                int c0 = 8 * t + 2 * (lane & 3);
                if (c0 > lr)          s[t][0] = -1e30f;
                if (c0 + 1 > lr)      s[t][1] = -1e30f;
                if (c0 > lr + 8)      s[t][2] = -1e30f;
                if (c0 + 1 > lr + 8)  s[t][3] = -1e30f;
            }
        }
        float mx0 = m0, mx1 = m1;
#pragma unroll
        for (int t = 0; t < 8; t++) {
            mx0 = fmaxf(mx0, fmaxf(s[t][0], s[t][1]));
            mx1 = fmaxf(mx1, fmaxf(s[t][2], s[t][3]));
        }
        mx0 = fmaxf(mx0, __shfl_xor_sync(0xffffffffu, mx0, 1));
        mx0 = fmaxf(mx0, __shfl_xor_sync(0xffffffffu, mx0, 2));
        mx1 = fmaxf(mx1, __shfl_xor_sync(0xffffffffu, mx1, 1));
        mx1 = fmaxf(mx1, __shfl_xor_sync(0xffffffffu, mx1, 2));

        float a0 = __expf(m0 - mx0), a1 = __expf(m1 - mx1);
        m0 = mx0; m1 = mx1;

        float rs0 = 0.f, rs1 = 0.f;
        uint32_t pH[4][4], pL[4][4];
#pragma unroll
        for (int t = 0; t < 8; t++) {
            float p0 = __expf(s[t][0] - mx0), p1 = __expf(s[t][1] - mx0);
            float p2 = __expf(s[t][2] - mx1), p3 = __expf(s[t][3] - mx1);
            rs0 += p0 + p1; rs1 += p2 + p3;
            float h0 = __bfloat162float(__float2bfloat16(p0));
            float h1 = __bfloat162float(__float2bfloat16(p1));
            float h2 = __bfloat162float(__float2bfloat16(p2));
            float h3 = __bfloat162float(__float2bfloat16(p3));
            int u = t >> 1, e = (t & 1) * 2;
            pH[u][e]     = pack_bf16(h0, h1);
            pH[u][e + 1] = pack_bf16(h2, h3);
            pL[u][e]     = pack_bf16(p0 - h0, p1 - h1);
            pL[u][e + 1] = pack_bf16(p2 - h2, p3 - h3);
        }
        rs0 += __shfl_xor_sync(0xffffffffu, rs0, 1);
        rs0 += __shfl_xor_sync(0xffffffffu, rs0, 2);
        rs1 += __shfl_xor_sync(0xffffffffu, rs1, 1);
        rs1 += __shfl_xor_sync(0xffffffffu, rs1, 2);
        l0 = l0 * a0 + rs0;
        l1 = l1 * a1 + rs1;
#pragma unroll
        for (int t = 0; t < 16; t++) {
            o[t][0] *= a0; o[t][1] *= a0; o[t][2] *= a1; o[t][3] *= a1;
        }

#pragma unroll
        for (int u = 0; u < 4; u++) {
#pragma unroll
            for (int g = 0; g < 8; g++) {
                uint32_t voff = (uint32_t)(g * 16 + (lane & 7) + ((lane >> 4) << 3)) *
                                (SKV * 2) + u * 32 + ((lane >> 3) & 1) * 16;
                uint32_t bh[4], bl[4];
                ldsm4(bh, bVh + voff);
                ldsm4(bl, bVl + voff);
                mma_bf16(o[2 * g],     pH[u], bh[0], bh[1]);
                mma_bf16(o[2 * g],     pH[u], bl[0], bl[1]);
                mma_bf16(o[2 * g],     pL[u], bh[0], bh[1]);
                mma_bf16(o[2 * g + 1], pH[u], bh[2], bh[3]);
                mma_bf16(o[2 * g + 1], pH[u], bl[2], bl[3]);
                mma_bf16(o[2 * g + 1], pL[u], bh[2], bh[3]);
            }
        }
    }

    float inv0 = 1.f / l0, inv1 = 1.f / l1;
    int r = qi * 64 + warp * 16 + (lane >> 2);
#pragma unroll
    for (int t = 0; t < 16; t++) {
        int d = 8 * t + 2 * (lane & 3);
        size_t o0 = (size_t)r * (NHEAD * HDIM) + h * HDIM + d;
        size_t o1 = (size_t)(r + 8) * (NHEAD * HDIM) + h * HDIM + d;
        float v0 = o[t][0] * inv0, v1 = o[t][1] * inv0;
        float v2 = o[t][2] * inv1, v3 = o[t][3] * inv1;
        float h0 = __bfloat162float(__float2bfloat16(v0));
        float h1 = __bfloat162float(__float2bfloat16(v1));
        float h2 = __bfloat162float(__float2bfloat16(v2));
        float h3 = __bfloat162float(__float2bfloat16(v3));
        *(uint32_t*)(Oh + o0) = pack_bf16(h0, h1);
        *(uint32_t*)(Ol + o0) = pack_bf16(v0 - h0, v1 - h1);
        *(uint32_t*)(Oh + o1) = pack_bf16(h2, h3);
        *(uint32_t*)(Ol + o1) = pack_bf16(v2 - h2, v3 - h3);
    }
}

// ===========================================================================
extern "C" void kernel_launch(void* const* d_in, const int* in_sizes, int n_in,
                              void* d_out, int out_size)
{
    const float* hs  = (const float*)d_in[0];
    const float* wq  = (const float*)d_in[2];
    const float* wk  = (const float*)d_in[3];
    const float* wv  = (const float*)d_in[4];
    const float* wo  = (const float*)d_in[5];
    const float* qnw = (const float*)d_in[6];
    const float* knw = (const float*)d_in[7];
    float* out = (float*)d_out;

    float *gq, *gq2, *gk, *gk2, *gv, *gv2;
    cudaGetSymbolAddress((void**)&gq,  g_q);  cudaGetSymbolAddress((void**)&gq2, g_q2);
    cudaGetSymbolAddress((void**)&gk,  g_k);  cudaGetSymbolAddress((void**)&gk2, g_k2);
    cudaGetSymbolAddress((void**)&gv,  g_v);  cudaGetSymbolAddress((void**)&gv2, g_v2);

    __nv_bfloat16 *aoh, *aol, *qh2, *ql2, *kh2, *kl2, *vth, *vtl;
    cudaGetSymbolAddress((void**)&aoh, g_aoh); cudaGetSymbolAddress((void**)&aol, g_aol);
    cudaGetSymbolAddress((void**)&qh2, g_qh2); cudaGetSymbolAddress((void**)&ql2, g_ql2);
    cudaGetSymbolAddress((void**)&kh2, g_kh2); cudaGetSymbolAddress((void**)&kl2, g_kl2);
    cudaGetSymbolAddress((void**)&vth, g_vth); cudaGetSymbolAddress((void**)&vtl, g_vtl);

    cudaFuncSetAttribute(qkv_gemm,
                         cudaFuncAttributeMaxDynamicSharedMemorySize, GEMM_SMEM);
    cudaFuncSetAttribute(o_gemm,
                         cudaFuncAttributeMaxDynamicSharedMemorySize, GEMM_SMEM);
    cudaFuncSetAttribute(flash_mma,
                         cudaFuncAttributeMaxDynamicSharedMemorySize, FLASH_SMEM);

    // 1. RoPE table
    rope_table_kernel<<<SEQ * 64 / 256, 256>>>();
    // 2. split hs + wq + wk + wv
    split_a<<<TOTA4 / 256, 256>>>(hs, wq, wk, wv);
    // 3. split wo
    split_wo<<<WO4 / 256, 256>>>(wo);
    // 4. fused QKV projection, split-K=2, pipelined frags  <- ncu capture slot
    qkv_gemm<<<dim3(32, 32), 256, GEMM_SMEM>>>();
    // 5-7. RMSNorm+RoPE on summed partials -> bf16 operands; V transpose+split
    qk_norm_rope_split<<<dim3(SEQ, NHEAD), 128>>>(gq, gq2, qnw, qh2, ql2, NHEAD,
                                                  0.08838834764831845f);
    qk_norm_rope_split<<<dim3(SEQ, NKVH), 128>>>(gk, gk2, knw, kh2, kl2, NKVH, 1.0f);
    v_split_t<<<dim3(SEQ / 32, HDIM / 32, NKVH), dim3(32, 8)>>>(gv, gv2, vth, vtl);
    // 8. flash attention -> bf16 hi/lo AO
    flash_mma<<<dim3(SEQ / 64, NHEAD), 128, FLASH_SMEM>>>(qh2, ql2, kh2, kl2,
                                                          vth, vtl, aoh, aol);
    // 9. O projection, split-K=4 into partials
    o_gemm<<<dim3(16, 64), 256, GEMM_SMEM>>>();
    // 10. sum partials -> out
    add4<<<SEQ * HIDDEN / 1024, 256>>>(out);
}